// round 16
// baseline (speedup 1.0000x reference)
#include <cuda_runtime.h>
#include <cuda_fp16.h>

// Problem constants
#define BB   2
#define NN   2048
#define MM   1024
#define HH   16
#define DKK  64
#define ROWS (BB*NN)   // 4096

// Scratch (allocation-free rule: __device__ globals) — all fp16
__device__ __half g_q [BB*HH*NN*DKK];     // Q, pre-scaled by 0.125*log2(e)
__device__ __half g_k [BB*HH*NN*DKK];
__device__ __half g_v [BB*HH*NN*DKK];
__device__ __half g_ath[BB*NN*MM];        // attention output (concat layout)
__device__ __half g_xh[ROWS*MM];          // fp16 x
__device__ __half g_wh[4*MM*MM];          // fp16 Wq,Wk,Wv,Wo
__device__ __half g_mh[BB*NN*NN];         // fp16 mask

// ===========================================================================
// Helpers
// ===========================================================================
__device__ __forceinline__ unsigned smem_u32(const void* p) {
    unsigned a;
    asm("{ .reg .u64 t; cvta.to.shared.u64 t, %1; cvt.u32.u64 %0, t; }"
        : "=r"(a) : "l"(p));
    return a;
}
__device__ __forceinline__ float ex2f(float x) {
    float r;
    asm("ex2.approx.f32 %0, %1;" : "=f"(r) : "f"(x));
    return r;
}
__device__ __forceinline__ unsigned pack_f16(float lo, float hi) {
    unsigned r;
    asm("cvt.rn.f16x2.f32 %0, %1, %2;" : "=r"(r) : "f"(hi), "f"(lo));
    return r;
}
__device__ __forceinline__ void cp16(unsigned dst, const void* src) {
    asm volatile("cp.async.cg.shared.global [%0], [%1], 16;"
                 :: "r"(dst), "l"(src));
}
#define CP_COMMIT() asm volatile("cp.async.commit_group;" ::: "memory")
#define CP_WAIT1()  asm volatile("cp.async.wait_group 1;" ::: "memory")
#define CP_WAIT0()  asm volatile("cp.async.wait_group 0;" ::: "memory")

// ldmatrix variants
__device__ __forceinline__ void ldm4(unsigned& r0, unsigned& r1,
                                     unsigned& r2, unsigned& r3, unsigned addr)
{
    asm volatile("ldmatrix.sync.aligned.m8n8.x4.shared.b16 {%0,%1,%2,%3}, [%4];"
                 : "=r"(r0), "=r"(r1), "=r"(r2), "=r"(r3) : "r"(addr));
}
__device__ __forceinline__ void ldm4t(unsigned& r0, unsigned& r1,
                                      unsigned& r2, unsigned& r3, unsigned addr)
{
    asm volatile("ldmatrix.sync.aligned.m8n8.x4.trans.shared.b16 {%0,%1,%2,%3}, [%4];"
                 : "=r"(r0), "=r"(r1), "=r"(r2), "=r"(r3) : "r"(addr));
}
__device__ __forceinline__ void ldm2t(unsigned& r0, unsigned& r1, unsigned addr)
{
    asm volatile("ldmatrix.sync.aligned.m8n8.x2.trans.shared.b16 {%0,%1}, [%2];"
                 : "=r"(r0), "=r"(r1) : "r"(addr));
}

// m16n8k16 fp16 MMA, f32 accumulate.
__device__ __forceinline__ void mma16h(float* d, unsigned a0, unsigned a1,
                                       unsigned a2, unsigned a3,
                                       unsigned b0, unsigned b1)
{
    asm("mma.sync.aligned.m16n8k16.row.col.f32.f16.f16.f32 "
        "{%0,%1,%2,%3},{%4,%5,%6,%7},{%8,%9},{%0,%1,%2,%3};"
        : "+f"(d[0]), "+f"(d[1]), "+f"(d[2]), "+f"(d[3])
        : "r"(a0), "r"(a1), "r"(a2), "r"(a3), "r"(b0), "r"(b1));
}

// Lane-constant ldmatrix address offsets (bytes), stride GSTRH halves.
#define GSTRH 72
__device__ __forceinline__ unsigned ldm_aoff(int lane) {
    const int r = (lane & 7) + ((lane >> 3) & 1) * 8;
    const int k = (lane >> 4) * 8;
    return (unsigned)(r * GSTRH + k) * 2u;
}
__device__ __forceinline__ unsigned ldm_boff(int lane) {
    const int r = (lane & 7) + (lane >> 4) * 8;
    const int k = ((lane >> 3) & 1) * 8;
    return (unsigned)(r * GSTRH + k) * 2u;
}
// ones columns 64..71 of V tile, x2-trans (lanes 0..15 -> kv rows 0..15)
__device__ __forceinline__ unsigned ldm_ooff(int lane) {
    return (unsigned)((lane & 15) * GSTRH + 64) * 2u;
}

// ===========================================================================
// Prep: fp32 -> fp16 (rn), elementwise
// ===========================================================================
__global__ __launch_bounds__(256) void cvt_f16_kernel(
    const float* __restrict__ src, __half* __restrict__ dst, int n4)
{
    const int i = blockIdx.x * blockDim.x + threadIdx.x;
    if (i < n4) {
        float4 v = ((const float4*)src)[i];
        uint2 p = { pack_f16(v.x, v.y), pack_f16(v.z, v.w) };
        *(uint2*)(dst + (size_t)i * 4) = p;
    }
}
__global__ __launch_bounds__(256) void cvt_w_kernel(
    const float* __restrict__ W0, const float* __restrict__ W1,
    const float* __restrict__ W2, const float* __restrict__ W3,
    __half* __restrict__ dst)
{
    const int z = blockIdx.y;
    const float* src = (z == 0) ? W0 : (z == 1) ? W1 : (z == 2) ? W2 : W3;
    const int i = blockIdx.x * blockDim.x + threadIdx.x;
    if (i < MM*MM/4) {
        float4 v = ((const float4*)src)[i];
        uint2 p = { pack_f16(v.x, v.y), pack_f16(v.z, v.w) };
        *(uint2*)(dst + (size_t)z * MM * MM + (size_t)i * 4) = p;
    }
}

// ===========================================================================
// fp16 GEMM body: CTA 128x128, 4 warps, warp tile 64x64, K-chunk 64,
// cp.async double buffer, single barrier per chunk, ldmatrix loads.
// __launch_bounds__(128, 3): reg cap 170 -> 3 CTAs/SM (12 warps/SM).
// ===========================================================================
#define GBUFH (128*GSTRH)            // 9216 halves per buffer
#define GEMM_SMEM (4*GBUFH*2)        // 73728 bytes

__device__ __forceinline__ void gemm_cp_chunk(
    unsigned sA, unsigned sW,
    const __half* __restrict__ A, const __half* __restrict__ W,
    int tid, int row0, int col0, int chunk)
{
    #pragma unroll
    for (int k = 0; k < 8; k++) {
        const int u = tid + k * 128;
        const int r = u >> 3;
        const int c = u & 7;
        const unsigned soff = (unsigned)(r * GSTRH + c * 8) * 2u;
        cp16(sA + soff, A + (size_t)(row0 + r) * MM + chunk * 64 + c * 8);
        cp16(sW + soff, W + (size_t)(col0 + r) * MM + chunk * 64 + c * 8);
    }
}

template<int HEADED>
__device__ __forceinline__ void gemm_body(
    const __half* __restrict__ A, const __half* __restrict__ W,
    const float* __restrict__ bias, void* __restrict__ Cv, float oscale)
{
    extern __shared__ __half hs[];
    const unsigned sbase = smem_u32(hs);

    const int tid  = threadIdx.x;
    const int w    = tid >> 5;
    const int lane = tid & 31;
    const int g    = lane >> 2;
    const int t    = lane & 3;
    const int row0 = blockIdx.y * 128;
    const int col0 = blockIdx.x * 128;
    const int wm   = (w >> 1) * 64;
    const int wn   = (w & 1) * 64;
    const unsigned aoff = ldm_aoff(lane);
    const unsigned boff = ldm_boff(lane);

    float c[4][8][4] = {};

    gemm_cp_chunk(sbase, sbase + 2*GBUFH*2u, A, W, tid, row0, col0, 0);
    CP_COMMIT();

    for (int i = 0; i < 16; i++) {
        const int cur = i & 1;
        CP_WAIT0();
        __syncthreads();
        if (i + 1 < 16) {
            const int nxt = 1 - cur;
            gemm_cp_chunk(sbase + nxt*GBUFH*2u, sbase + (2+nxt)*GBUFH*2u,
                          A, W, tid, row0, col0, i + 1);
            CP_COMMIT();
        }

        const unsigned sAb = sbase + (unsigned)cur * GBUFH * 2u;
        const unsigned sWb = sbase + (unsigned)(2 + cur) * GBUFH * 2u;

        #pragma unroll
        for (int ks = 0; ks < 4; ks++) {
            const unsigned kboff = (unsigned)(ks * 16) * 2u;
            unsigned a[4][4];
            #pragma unroll
            for (int mt = 0; mt < 4; mt++)
                ldm4(a[mt][0], a[mt][1], a[mt][2], a[mt][3],
                     sAb + (unsigned)((wm + mt*16) * GSTRH) * 2u + kboff + aoff);
            #pragma unroll
            for (int p = 0; p < 4; p++) {
                unsigned b0, b1, b2, b3;
                ldm4(b0, b1, b2, b3,
                     sWb + (unsigned)((wn + p*16) * GSTRH) * 2u + kboff + boff);
                #pragma unroll
                for (int mt = 0; mt < 4; mt++) {
                    mma16h(c[mt][2*p],   a[mt][0], a[mt][1], a[mt][2], a[mt][3], b0, b1);
                    mma16h(c[mt][2*p+1], a[mt][0], a[mt][1], a[mt][2], a[mt][3], b2, b3);
                }
            }
        }
    }

    // Epilogue
    #pragma unroll
    for (int mt = 0; mt < 4; mt++) {
        const int r0 = row0 + wm + mt * 16 + g;
        const int r1 = r0 + 8;
        #pragma unroll
        for (int nt = 0; nt < 8; nt++) {
            const int col = col0 + wn + nt * 8 + 2 * t;
            const float bx = bias[col], by = bias[col + 1];
            if (HEADED) {
                __half* C = (__half*)Cv;
                const unsigned p0 = pack_f16((c[mt][nt][0] + bx) * oscale,
                                             (c[mt][nt][1] + by) * oscale);
                const unsigned p1 = pack_f16((c[mt][nt][2] + bx) * oscale,
                                             (c[mt][nt][3] + by) * oscale);
                const int h = col >> 6;
                const int d = col & 63;
                const int b0r = r0 >> 11, n0r = r0 & (NN - 1);
                const int b1r = r1 >> 11, n1r = r1 & (NN - 1);
                *(unsigned*)(C + (((size_t)(b0r*HH + h))*NN + n0r)*DKK + d) = p0;
                *(unsigned*)(C + (((size_t)(b1r*HH + h))*NN + n1r)*DKK + d) = p1;
            } else {
                float* C = (float*)Cv;
                float2 v0 = { c[mt][nt][0] + bx, c[mt][nt][1] + by };
                float2 v1 = { c[mt][nt][2] + bx, c[mt][nt][3] + by };
                *(float2*)(C + (size_t)r0 * MM + col) = v0;
                *(float2*)(C + (size_t)r1 * MM + col) = v1;
            }
        }
    }
}

__global__ __launch_bounds__(128, 3) void qkv_mma_kernel(
    const __half* __restrict__ A, const __half* __restrict__ Wt,
    const float* __restrict__ bq, const float* __restrict__ bk,
    const float* __restrict__ bv, float qscale)
{
    const int z = blockIdx.z;
    const __half* W   = Wt + (size_t)z * MM * MM;
    const float* bias = (z == 0) ? bq : (z == 1) ? bk : bv;
    __half*      C    = (z == 0) ? g_q : (z == 1) ? g_k : g_v;
    gemm_body<1>(A, W, bias, C, (z == 0) ? qscale : 1.0f);
}

__global__ __launch_bounds__(128, 3) void out_mma_kernel(
    const __half* __restrict__ A, const __half* __restrict__ W,
    const float* __restrict__ bias, float* __restrict__ C)
{
    gemm_body<0>(A, W, bias, C, 1.0f);
}

// ===========================================================================
// Flash attention, all-fp16 MMA, ldmatrix loads, no online softmax.
// CTA = 128 q-rows, 4 warps (warp = 32 rows). kv tile 64.
// K/V: 3-stage cp.async ring. MASK: 2-stage cp.async ring (fp16, one iter
// ahead; frags via ldmatrix.x4 — A-frag layout == S C-frag). One barrier
// per iteration. V natural layout + trans-ldmatrix; ones COLUMN in V pad
// -> tensor-pipe rowsums.
// ===========================================================================
#define HQ_OFF  0
#define HK_OFF  9216
#define HKBUF   4608
#define HV_OFF  23040
#define HVBUF   4608
#define HM_OFF  36864
#define HMBUF   9216
#define FLASH_SMEM (55296 * 2)   // 110592 bytes

__device__ __forceinline__ void flash_cp_q(
    unsigned sQ, const __half* __restrict__ Qg, int tid, int q0)
{
    #pragma unroll
    for (int j = 0; j < 8; j++) {
        const int u = tid + j * 128;
        const int r = u >> 3;
        const int c = u & 7;
        cp16(sQ + (unsigned)(r * GSTRH + c * 8) * 2u,
             Qg + (size_t)(q0 + r) * DKK + c * 8);
    }
}
__device__ __forceinline__ void flash_cp_kv(
    unsigned sK, unsigned sV,
    const __half* __restrict__ Kg, const __half* __restrict__ Vg,
    int tid, int k0)
{
    #pragma unroll
    for (int j = 0; j < 4; j++) {
        const int u = tid + j * 128;
        const int r = u >> 3;
        const int c = u & 7;
        const unsigned soff = (unsigned)(r * GSTRH + c * 8) * 2u;
        cp16(sK + soff, Kg + (size_t)(k0 + r) * DKK + c * 8);
        cp16(sV + soff, Vg + (size_t)(k0 + r) * DKK + c * 8);
    }
}
__device__ __forceinline__ void flash_cp_m(
    unsigned sM, const __half* __restrict__ Mg, int tid, int q0, int k0)
{
    #pragma unroll
    for (int j = 0; j < 8; j++) {
        const int u = tid + j * 128;
        const int r = u >> 3;
        const int c = u & 7;
        cp16(sM + (unsigned)(r * GSTRH + c * 8) * 2u,
             Mg + (size_t)(q0 + r) * NN + k0 + c * 8);
    }
}

__global__ __launch_bounds__(128, 2) void flash_mma_kernel(
    const __half* __restrict__ maskh, __half* __restrict__ out)
{
    extern __shared__ __half hs[];
    const unsigned sbase = smem_u32(hs);

    const int tid  = threadIdx.x;
    const int w    = tid >> 5;
    const int lane = tid & 31;
    const int g    = lane >> 2;
    const int t    = lane & 3;
    const int q0   = blockIdx.x * 128;
    const int h    = blockIdx.y;
    const int b    = blockIdx.z;
    const unsigned aoff = ldm_aoff(lane);
    const unsigned boff = ldm_boff(lane);
    const unsigned ooff = ldm_ooff(lane);

    const __half* Qg = g_q + (((size_t)(b*HH + h)) * NN) * DKK;
    const __half* Kg = g_k + (((size_t)(b*HH + h)) * NN) * DKK;
    const __half* Vg = g_v + (((size_t)(b*HH + h)) * NN) * DKK;
    const __half* Mg = maskh + (size_t)b * NN * NN;

    // V pad COLS 64..71 for all 3 buffers: col 64 = 1.0, cols 65..71 = 0.
    {
        const __half one  = __float2half(1.0f);
        const __half zero = __float2half(0.0f);
        for (int u = tid; u < 3 * 64 * 8; u += 128) {
            const int buf = u / (64 * 8);
            const int r   = (u / 8) % 64;
            const int c   = 64 + (u & 7);
            hs[HV_OFF + buf * HVBUF + r * GSTRH + c] = (c == 64) ? one : zero;
        }
    }
    __syncthreads();

    // Prologue: G0 = kv0 + mask0, G1 = kv1.
    flash_cp_q(sbase + HQ_OFF*2u, Qg, tid, q0);
    flash_cp_kv(sbase + HK_OFF*2u, sbase + HV_OFF*2u, Kg, Vg, tid, 0);
    flash_cp_m(sbase + HM_OFF*2u, Mg, tid, q0, 0);
    CP_COMMIT();
    flash_cp_kv(sbase + (HK_OFF + HKBUF)*2u, sbase + (HV_OFF + HVBUF)*2u,
                Kg, Vg, tid, 64);
    CP_COMMIT();

    float o[2][8][4] = {};
    float ol[2][4] = {};

    const int qw = q0 + w * 32;

    for (int it = 0; it < 32; it++) {
        const int k0   = it * 64;
        const int cur  = it % 3;
        const int mcur = it & 1;
        if (it < 31) { CP_WAIT1(); } else { CP_WAIT0(); }
        __syncthreads();

        if (it + 1 < 32) {
            flash_cp_m(sbase + (HM_OFF + (1 - mcur) * HMBUF) * 2u,
                       Mg, tid, q0, k0 + 64);
            CP_COMMIT();
        }
        if (it + 2 < 32) {
            const int nb = (it + 2) % 3;
            flash_cp_kv(sbase + (HK_OFF + nb*HKBUF)*2u,
                        sbase + (HV_OFF + nb*HVBUF)*2u, Kg, Vg, tid, k0 + 128);
            CP_COMMIT();
        }

        const unsigned sK = sbase + (unsigned)(HK_OFF + cur * HKBUF) * 2u;
        const unsigned sV = sbase + (unsigned)(HV_OFF + cur * HVBUF) * 2u;
        const unsigned sM = sbase + (unsigned)(HM_OFF + mcur * HMBUF) * 2u;

        // ---- S~ = Qs * K^T ----
        float s[2][8][4] = {};
        #pragma unroll
        for (int ks = 0; ks < 4; ks++) {
            const unsigned kboff = (unsigned)(ks * 16) * 2u;
            unsigned aq[2][4];
            #pragma unroll
            for (int mt = 0; mt < 2; mt++)
                ldm4(aq[mt][0], aq[mt][1], aq[mt][2], aq[mt][3],
                     sbase + (unsigned)((HQ_OFF + (w*32 + mt*16) * GSTRH)) * 2u
                           + kboff + aoff);
            #pragma unroll
            for (int p = 0; p < 4; p++) {
                unsigned b0, b1, b2, b3;
                ldm4(b0, b1, b2, b3,
                     sK + (unsigned)(p * 16 * GSTRH) * 2u + kboff + boff);
                mma16h(s[0][2*p],   aq[0][0], aq[0][1], aq[0][2], aq[0][3], b0, b1);
                mma16h(s[0][2*p+1], aq[0][0], aq[0][1], aq[0][2], aq[0][3], b2, b3);
                mma16h(s[1][2*p],   aq[1][0], aq[1][1], aq[1][2], aq[1][3], b0, b1);
                mma16h(s[1][2*p+1], aq[1][0], aq[1][1], aq[1][2], aq[1][3], b2, b3);
            }
        }

        // ---- p = exp2(s~ * mask), mask frags via ldmatrix (A-frag layout) ----
        #pragma unroll
        for (int mt = 0; mt < 2; mt++) {
            const unsigned sMr = sM + (unsigned)((w*32 + mt*16) * GSTRH) * 2u;
            #pragma unroll
            for (int p = 0; p < 4; p++) {
                unsigned m0, m1, m2, m3;
                ldm4(m0, m1, m2, m3, sMr + (unsigned)(p * 16) * 2u + aoff);
                float2 f0 = __half22float2(*(__half2*)&m0);
                float2 f1 = __half22float2(*(__half2*)&m1);
                float2 f2 = __half22float2(*(__half2*)&m2);
                float2 f3 = __half22float2(*(__half2*)&m3);
                s[mt][2*p][0]   = ex2f(s[mt][2*p][0]   * f0.x);
                s[mt][2*p][1]   = ex2f(s[mt][2*p][1]   * f0.y);
                s[mt][2*p][2]   = ex2f(s[mt][2*p][2]   * f1.x);
                s[mt][2*p][3]   = ex2f(s[mt][2*p][3]   * f1.y);
                s[mt][2*p+1][0] = ex2f(s[mt][2*p+1][0] * f2.x);
                s[mt][2*p+1][1] = ex2f(s[mt][2*p+1][1] * f2.y);
                s[mt][2*p+1][2] = ex2f(s[mt][2*p+1][2] * f3.x);
                s[mt][2*p+1][3] = ex2f(s[mt][2*p+1][3] * f3.y);
            }
        }

        // ---- O += P * V  (trans-ldmatrix B from natural-layout V) ----
        #pragma unroll
        for (int kk = 0; kk < 4; kk++) {
            unsigned a[2][4];
            #pragma unroll
            for (int mt = 0; mt < 2; mt++) {
                a[mt][0] = pack_f16(s[mt][2*kk][0],   s[mt][2*kk][1]);
                a[mt][1] = pack_f16(s[mt][2*kk][2],   s[mt][2*kk][3]);
                a[mt][2] = pack_f16(s[mt][2*kk+1][0], s[mt][2*kk+1][1]);
                a[mt][3] = pack_f16(s[mt][2*kk+1][2], s[mt][2*kk+1][3]);
            }
            const unsigned krow = (unsigned)(kk * 16 * GSTRH) * 2u;
            #pragma unroll
            for (int p = 0; p < 4; p++) {
                unsigned b0, b1, b2, b3;
                ldm4t(b0, b1, b2, b3,
                      sV + krow + (unsigned)(p * 16) * 2u + aoff);
                mma16h(o[0][2*p],   a[0][0], a[0][1], a[0][2], a[0][3], b0, b1);
                mma16h(o[0][2*p+1], a[0][0], a[0][1], a[0][2], a[0][3], b2, b3);
                mma16h(o[1][2*p],   a[1][0], a[1][1], a[1][2], a[1][3], b0, b1);
                mma16h(o[1][2*p+1], a[1][0], a[1][1], a[1][2], a[1][3], b2, b3);
            }
            {
                unsigned b0, b1;
                ldm2t(b0, b1, sV + krow + ooff);
                mma16h(ol[0], a[0][0], a[0][1], a[0][2], a[0][3], b0, b1);
                mma16h(ol[1], a[1][0], a[1][1], a[1][2], a[1][3], b0, b1);
            }
        }
    }

    // ---- l broadcast + normalize + write concat [B,N,M] fp16 ----
    #pragma unroll
    for (int mt = 0; mt < 2; mt++) {
        const float l0 = __shfl_sync(0xffffffffu, ol[mt][0], lane & 28);
        const float l1 = __shfl_sync(0xffffffffu, ol[mt][2], lane & 28);
        const float il0 = 1.0f / l0;
        const float il1 = 1.0f / l1;
        __half* Or0 = out + ((size_t)b * NN + qw + mt*16 + g) * MM + h * DKK;
        __half* Or1 = Or0 + 8 * MM;
        #pragma unroll
        for (int nt = 0; nt < 8; nt++) {
            const unsigned p0 = pack_f16(o[mt][nt][0] * il0, o[mt][nt][1] * il0);
            const unsigned p1 = pack_f16(o[mt][nt][2] * il1, o[mt][nt][3] * il1);
            *(unsigned*)(Or0 + nt * 8 + 2 * t) = p0;
            *(unsigned*)(Or1 + nt * 8 + 2 * t) = p1;
        }
    }
}

// ===========================================================================
extern "C" void kernel_launch(void* const* d_in, const int* in_sizes, int n_in,
                              void* d_out, int out_size)
{
    const float* x    = (const float*)d_in[0];
    const float* mask = (const float*)d_in[1];
    const float* Wq   = (const float*)d_in[2];
    const float* bq   = (const float*)d_in[3];
    const float* Wk   = (const float*)d_in[4];
    const float* bk   = (const float*)d_in[5];
    const float* Wv   = (const float*)d_in[6];
    const float* bv   = (const float*)d_in[7];
    const float* Wo   = (const float*)d_in[8];
    const float* bo   = (const float*)d_in[9];
    float* out = (float*)d_out;

    void *pxh, *pwh, *path, *pmh;
    cudaGetSymbolAddress(&pxh,  g_xh);
    cudaGetSymbolAddress(&pwh,  g_wh);
    cudaGetSymbolAddress(&path, g_ath);
    cudaGetSymbolAddress(&pmh,  g_mh);
    __half* xh  = (__half*)pxh;
    __half* wh  = (__half*)pwh;
    __half* ath = (__half*)path;
    __half* mh  = (__half*)pmh;

    cudaFuncSetAttribute(qkv_mma_kernel,
                         cudaFuncAttributeMaxDynamicSharedMemorySize, GEMM_SMEM);
    cudaFuncSetAttribute(out_mma_kernel,
                         cudaFuncAttributeMaxDynamicSharedMemorySize, GEMM_SMEM);
    cudaFuncSetAttribute(flash_mma_kernel,
                         cudaFuncAttributeMaxDynamicSharedMemorySize, FLASH_SMEM);

    // Convert inputs to fp16 once.
    cvt_f16_kernel<<<(ROWS*MM/4 + 255)/256, 256>>>(x, xh, ROWS*MM/4);
    cvt_f16_kernel<<<(BB*NN*NN/4 + 255)/256, 256>>>(mask, mh, BB*NN*NN/4);
    dim3 w_grid((MM*MM/4 + 255)/256, 4);
    cvt_w_kernel<<<w_grid, 256>>>(Wq, Wk, Wv, Wo, wh);

    // Fused Q/K/V projections (Q pre-scaled by 0.125*log2(e))
    const float qscale = 0.125f * 1.4426950408889634f;
    dim3 qkv_grid(MM/128, ROWS/128, 3);   // (8, 32, 3)
    qkv_mma_kernel<<<qkv_grid, 128, GEMM_SMEM>>>(xh, wh, bq, bk, bv, qscale);

    // Fused attention
    dim3 attn_grid(NN/128, HH, BB);       // (16, 16, 2)
    flash_mma_kernel<<<attn_grid, 128, FLASH_SMEM>>>(mh, ath);

    // Output projection (fp32 out)
    dim3 out_grid(MM/128, ROWS/128);      // (8, 32)
    out_mma_kernel<<<out_grid, 128, GEMM_SMEM>>>(ath, wh + 3*(size_t)MM*MM, bo, out);
}

// round 17
// speedup vs baseline: 1.0121x; 1.0121x over previous
#include <cuda_runtime.h>
#include <cuda_fp16.h>

// Problem constants
#define BB   2
#define NN   2048
#define MM   1024
#define HH   16
#define DKK  64
#define ROWS (BB*NN)   // 4096

// Scratch (allocation-free rule: __device__ globals) — all fp16
__device__ __half g_q [BB*HH*NN*DKK];     // Q, pre-scaled by 0.125*log2(e)
__device__ __half g_k [BB*HH*NN*DKK];
__device__ __half g_v [BB*HH*NN*DKK];
__device__ __half g_ath[BB*NN*MM];        // attention output (concat layout)
__device__ __half g_xh[ROWS*MM];          // fp16 x
__device__ __half g_wh[4*MM*MM];          // fp16 Wq,Wk,Wv,Wo
__device__ __half g_mh[BB*NN*NN];         // fp16 mask

// ===========================================================================
// Helpers
// ===========================================================================
__device__ __forceinline__ unsigned smem_u32(const void* p) {
    unsigned a;
    asm("{ .reg .u64 t; cvta.to.shared.u64 t, %1; cvt.u32.u64 %0, t; }"
        : "=r"(a) : "l"(p));
    return a;
}
__device__ __forceinline__ unsigned pack_f16(float lo, float hi) {
    unsigned r;
    asm("cvt.rn.f16x2.f32 %0, %1, %2;" : "=r"(r) : "f"(hi), "f"(lo));
    return r;
}
__device__ __forceinline__ unsigned hmul2u(unsigned a, unsigned b) {
    unsigned r;
    asm("mul.rn.f16x2 %0, %1, %2;" : "=r"(r) : "r"(a), "r"(b));
    return r;
}
__device__ __forceinline__ unsigned h2exp2u(unsigned x) {
    unsigned r;
    asm("ex2.approx.f16x2 %0, %1;" : "=r"(r) : "r"(x));
    return r;
}
__device__ __forceinline__ void cp16(unsigned dst, const void* src) {
    asm volatile("cp.async.cg.shared.global [%0], [%1], 16;"
                 :: "r"(dst), "l"(src));
}
#define CP_COMMIT() asm volatile("cp.async.commit_group;" ::: "memory")
#define CP_WAIT1()  asm volatile("cp.async.wait_group 1;" ::: "memory")
#define CP_WAIT0()  asm volatile("cp.async.wait_group 0;" ::: "memory")

// ldmatrix variants
__device__ __forceinline__ void ldm4(unsigned& r0, unsigned& r1,
                                     unsigned& r2, unsigned& r3, unsigned addr)
{
    asm volatile("ldmatrix.sync.aligned.m8n8.x4.shared.b16 {%0,%1,%2,%3}, [%4];"
                 : "=r"(r0), "=r"(r1), "=r"(r2), "=r"(r3) : "r"(addr));
}
__device__ __forceinline__ void ldm4t(unsigned& r0, unsigned& r1,
                                      unsigned& r2, unsigned& r3, unsigned addr)
{
    asm volatile("ldmatrix.sync.aligned.m8n8.x4.trans.shared.b16 {%0,%1,%2,%3}, [%4];"
                 : "=r"(r0), "=r"(r1), "=r"(r2), "=r"(r3) : "r"(addr));
}
__device__ __forceinline__ void ldm2t(unsigned& r0, unsigned& r1, unsigned addr)
{
    asm volatile("ldmatrix.sync.aligned.m8n8.x2.trans.shared.b16 {%0,%1}, [%2];"
                 : "=r"(r0), "=r"(r1) : "r"(addr));
}

// m16n8k16 fp16 MMA, f32 accumulate.
__device__ __forceinline__ void mma16h(float* d, unsigned a0, unsigned a1,
                                       unsigned a2, unsigned a3,
                                       unsigned b0, unsigned b1)
{
    asm("mma.sync.aligned.m16n8k16.row.col.f32.f16.f16.f32 "
        "{%0,%1,%2,%3},{%4,%5,%6,%7},{%8,%9},{%0,%1,%2,%3};"
        : "+f"(d[0]), "+f"(d[1]), "+f"(d[2]), "+f"(d[3])
        : "r"(a0), "r"(a1), "r"(a2), "r"(a3), "r"(b0), "r"(b1));
}

// Lane-constant ldmatrix address offsets (bytes), stride GSTRH halves.
#define GSTRH 72
__device__ __forceinline__ unsigned ldm_aoff(int lane) {
    const int r = (lane & 7) + ((lane >> 3) & 1) * 8;
    const int k = (lane >> 4) * 8;
    return (unsigned)(r * GSTRH + k) * 2u;
}
__device__ __forceinline__ unsigned ldm_boff(int lane) {
    const int r = (lane & 7) + (lane >> 4) * 8;
    const int k = ((lane >> 3) & 1) * 8;
    return (unsigned)(r * GSTRH + k) * 2u;
}
// ones columns 64..71 of V tile, x2-trans (lanes 0..15 -> kv rows 0..15)
__device__ __forceinline__ unsigned ldm_ooff(int lane) {
    return (unsigned)((lane & 15) * GSTRH + 64) * 2u;
}

// ===========================================================================
// Prep: fp32 -> fp16 (rn), elementwise
// ===========================================================================
__global__ __launch_bounds__(256) void cvt_f16_kernel(
    const float* __restrict__ src, __half* __restrict__ dst, int n4)
{
    const int i = blockIdx.x * blockDim.x + threadIdx.x;
    if (i < n4) {
        float4 v = ((const float4*)src)[i];
        uint2 p = { pack_f16(v.x, v.y), pack_f16(v.z, v.w) };
        *(uint2*)(dst + (size_t)i * 4) = p;
    }
}
__global__ __launch_bounds__(256) void cvt_w_kernel(
    const float* __restrict__ W0, const float* __restrict__ W1,
    const float* __restrict__ W2, const float* __restrict__ W3,
    __half* __restrict__ dst)
{
    const int z = blockIdx.y;
    const float* src = (z == 0) ? W0 : (z == 1) ? W1 : (z == 2) ? W2 : W3;
    const int i = blockIdx.x * blockDim.x + threadIdx.x;
    if (i < MM*MM/4) {
        float4 v = ((const float4*)src)[i];
        uint2 p = { pack_f16(v.x, v.y), pack_f16(v.z, v.w) };
        *(uint2*)(dst + (size_t)z * MM * MM + (size_t)i * 4) = p;
    }
}

// ===========================================================================
// fp16 GEMM body: CTA 128x128, 4 warps, warp tile 64x64, K-chunk 64,
// cp.async double buffer, single barrier per chunk, ldmatrix loads.
// ===========================================================================
#define GBUFH (128*GSTRH)            // 9216 halves per buffer
#define GEMM_SMEM (4*GBUFH*2)        // 73728 bytes

__device__ __forceinline__ void gemm_cp_chunk(
    unsigned sA, unsigned sW,
    const __half* __restrict__ A, const __half* __restrict__ W,
    int tid, int row0, int col0, int chunk)
{
    #pragma unroll
    for (int k = 0; k < 8; k++) {
        const int u = tid + k * 128;
        const int r = u >> 3;
        const int c = u & 7;
        const unsigned soff = (unsigned)(r * GSTRH + c * 8) * 2u;
        cp16(sA + soff, A + (size_t)(row0 + r) * MM + chunk * 64 + c * 8);
        cp16(sW + soff, W + (size_t)(col0 + r) * MM + chunk * 64 + c * 8);
    }
}

template<int HEADED>
__device__ __forceinline__ void gemm_body(
    const __half* __restrict__ A, const __half* __restrict__ W,
    const float* __restrict__ bias, void* __restrict__ Cv, float oscale)
{
    extern __shared__ __half hs[];
    const unsigned sbase = smem_u32(hs);

    const int tid  = threadIdx.x;
    const int w    = tid >> 5;
    const int lane = tid & 31;
    const int g    = lane >> 2;
    const int t    = lane & 3;
    const int row0 = blockIdx.y * 128;
    const int col0 = blockIdx.x * 128;
    const int wm   = (w >> 1) * 64;
    const int wn   = (w & 1) * 64;
    const unsigned aoff = ldm_aoff(lane);
    const unsigned boff = ldm_boff(lane);

    float c[4][8][4] = {};

    gemm_cp_chunk(sbase, sbase + 2*GBUFH*2u, A, W, tid, row0, col0, 0);
    CP_COMMIT();

    for (int i = 0; i < 16; i++) {
        const int cur = i & 1;
        CP_WAIT0();
        __syncthreads();
        if (i + 1 < 16) {
            const int nxt = 1 - cur;
            gemm_cp_chunk(sbase + nxt*GBUFH*2u, sbase + (2+nxt)*GBUFH*2u,
                          A, W, tid, row0, col0, i + 1);
            CP_COMMIT();
        }

        const unsigned sAb = sbase + (unsigned)cur * GBUFH * 2u;
        const unsigned sWb = sbase + (unsigned)(2 + cur) * GBUFH * 2u;

        #pragma unroll
        for (int ks = 0; ks < 4; ks++) {
            const unsigned kboff = (unsigned)(ks * 16) * 2u;
            unsigned a[4][4];
            #pragma unroll
            for (int mt = 0; mt < 4; mt++)
                ldm4(a[mt][0], a[mt][1], a[mt][2], a[mt][3],
                     sAb + (unsigned)((wm + mt*16) * GSTRH) * 2u + kboff + aoff);
            #pragma unroll
            for (int p = 0; p < 4; p++) {
                unsigned b0, b1, b2, b3;
                ldm4(b0, b1, b2, b3,
                     sWb + (unsigned)((wn + p*16) * GSTRH) * 2u + kboff + boff);
                #pragma unroll
                for (int mt = 0; mt < 4; mt++) {
                    mma16h(c[mt][2*p],   a[mt][0], a[mt][1], a[mt][2], a[mt][3], b0, b1);
                    mma16h(c[mt][2*p+1], a[mt][0], a[mt][1], a[mt][2], a[mt][3], b2, b3);
                }
            }
        }
    }

    // Epilogue
    #pragma unroll
    for (int mt = 0; mt < 4; mt++) {
        const int r0 = row0 + wm + mt * 16 + g;
        const int r1 = r0 + 8;
        #pragma unroll
        for (int nt = 0; nt < 8; nt++) {
            const int col = col0 + wn + nt * 8 + 2 * t;
            const float bx = bias[col], by = bias[col + 1];
            if (HEADED) {
                __half* C = (__half*)Cv;
                const unsigned p0 = pack_f16((c[mt][nt][0] + bx) * oscale,
                                             (c[mt][nt][1] + by) * oscale);
                const unsigned p1 = pack_f16((c[mt][nt][2] + bx) * oscale,
                                             (c[mt][nt][3] + by) * oscale);
                const int h = col >> 6;
                const int d = col & 63;
                const int b0r = r0 >> 11, n0r = r0 & (NN - 1);
                const int b1r = r1 >> 11, n1r = r1 & (NN - 1);
                *(unsigned*)(C + (((size_t)(b0r*HH + h))*NN + n0r)*DKK + d) = p0;
                *(unsigned*)(C + (((size_t)(b1r*HH + h))*NN + n1r)*DKK + d) = p1;
            } else {
                float* C = (float*)Cv;
                float2 v0 = { c[mt][nt][0] + bx, c[mt][nt][1] + by };
                float2 v1 = { c[mt][nt][2] + bx, c[mt][nt][3] + by };
                *(float2*)(C + (size_t)r0 * MM + col) = v0;
                *(float2*)(C + (size_t)r1 * MM + col) = v1;
            }
        }
    }
}

__global__ __launch_bounds__(128, 2) void qkv_mma_kernel(
    const __half* __restrict__ A, const __half* __restrict__ Wt,
    const float* __restrict__ bq, const float* __restrict__ bk,
    const float* __restrict__ bv, float qscale)
{
    const int z = blockIdx.z;
    const __half* W   = Wt + (size_t)z * MM * MM;
    const float* bias = (z == 0) ? bq : (z == 1) ? bk : bv;
    __half*      C    = (z == 0) ? g_q : (z == 1) ? g_k : g_v;
    gemm_body<1>(A, W, bias, C, (z == 0) ? qscale : 1.0f);
}

__global__ __launch_bounds__(128, 2) void out_mma_kernel(
    const __half* __restrict__ A, const __half* __restrict__ W,
    const float* __restrict__ bias, float* __restrict__ C)
{
    gemm_body<0>(A, W, bias, C, 1.0f);
}

// ===========================================================================
// Flash attention, all-fp16 MMA, ldmatrix loads, no online softmax.
// CTA = 128 q-rows, 4 warps (warp = 32 rows). kv tile 64.
// K/V: 3-stage cp.async ring. MASK: 2-stage cp.async ring (fp16 frags via
// ldmatrix; kept packed). P = ex2.approx.f16x2( s_h2 * m_h2 ): one MUFU op
// per 2 elements, result IS the PV A-fragment word. One barrier per iter.
// V natural layout + trans-ldmatrix; ones COLUMN in V pad -> MMA rowsums.
// ===========================================================================
#define HQ_OFF  0
#define HK_OFF  9216
#define HKBUF   4608
#define HV_OFF  23040
#define HVBUF   4608
#define HM_OFF  36864
#define HMBUF   9216
#define FLASH_SMEM (55296 * 2)   // 110592 bytes

__device__ __forceinline__ void flash_cp_q(
    unsigned sQ, const __half* __restrict__ Qg, int tid, int q0)
{
    #pragma unroll
    for (int j = 0; j < 8; j++) {
        const int u = tid + j * 128;
        const int r = u >> 3;
        const int c = u & 7;
        cp16(sQ + (unsigned)(r * GSTRH + c * 8) * 2u,
             Qg + (size_t)(q0 + r) * DKK + c * 8);
    }
}
__device__ __forceinline__ void flash_cp_kv(
    unsigned sK, unsigned sV,
    const __half* __restrict__ Kg, const __half* __restrict__ Vg,
    int tid, int k0)
{
    #pragma unroll
    for (int j = 0; j < 4; j++) {
        const int u = tid + j * 128;
        const int r = u >> 3;
        const int c = u & 7;
        const unsigned soff = (unsigned)(r * GSTRH + c * 8) * 2u;
        cp16(sK + soff, Kg + (size_t)(k0 + r) * DKK + c * 8);
        cp16(sV + soff, Vg + (size_t)(k0 + r) * DKK + c * 8);
    }
}
__device__ __forceinline__ void flash_cp_m(
    unsigned sM, const __half* __restrict__ Mg, int tid, int q0, int k0)
{
    #pragma unroll
    for (int j = 0; j < 8; j++) {
        const int u = tid + j * 128;
        const int r = u >> 3;
        const int c = u & 7;
        cp16(sM + (unsigned)(r * GSTRH + c * 8) * 2u,
             Mg + (size_t)(q0 + r) * NN + k0 + c * 8);
    }
}

__global__ __launch_bounds__(128, 2) void flash_mma_kernel(
    const __half* __restrict__ maskh, __half* __restrict__ out)
{
    extern __shared__ __half hs[];
    const unsigned sbase = smem_u32(hs);

    const int tid  = threadIdx.x;
    const int w    = tid >> 5;
    const int lane = tid & 31;
    const int g    = lane >> 2;
    const int t    = lane & 3;
    const int q0   = blockIdx.x * 128;
    const int h    = blockIdx.y;
    const int b    = blockIdx.z;
    const unsigned aoff = ldm_aoff(lane);
    const unsigned boff = ldm_boff(lane);
    const unsigned ooff = ldm_ooff(lane);

    const __half* Qg = g_q + (((size_t)(b*HH + h)) * NN) * DKK;
    const __half* Kg = g_k + (((size_t)(b*HH + h)) * NN) * DKK;
    const __half* Vg = g_v + (((size_t)(b*HH + h)) * NN) * DKK;
    const __half* Mg = maskh + (size_t)b * NN * NN;

    // V pad COLS 64..71 for all 3 buffers: col 64 = 1.0, cols 65..71 = 0.
    {
        const __half one  = __float2half(1.0f);
        const __half zero = __float2half(0.0f);
        for (int u = tid; u < 3 * 64 * 8; u += 128) {
            const int buf = u / (64 * 8);
            const int r   = (u / 8) % 64;
            const int c   = 64 + (u & 7);
            hs[HV_OFF + buf * HVBUF + r * GSTRH + c] = (c == 64) ? one : zero;
        }
    }
    __syncthreads();

    // Prologue: G0 = kv0 + mask0, G1 = kv1.
    flash_cp_q(sbase + HQ_OFF*2u, Qg, tid, q0);
    flash_cp_kv(sbase + HK_OFF*2u, sbase + HV_OFF*2u, Kg, Vg, tid, 0);
    flash_cp_m(sbase + HM_OFF*2u, Mg, tid, q0, 0);
    CP_COMMIT();
    flash_cp_kv(sbase + (HK_OFF + HKBUF)*2u, sbase + (HV_OFF + HVBUF)*2u,
                Kg, Vg, tid, 64);
    CP_COMMIT();

    float o[2][8][4] = {};
    float ol[2][4] = {};

    const int qw = q0 + w * 32;

    for (int it = 0; it < 32; it++) {
        const int k0   = it * 64;
        const int cur  = it % 3;
        const int mcur = it & 1;
        if (it < 31) { CP_WAIT1(); } else { CP_WAIT0(); }
        __syncthreads();

        if (it + 1 < 32) {
            flash_cp_m(sbase + (HM_OFF + (1 - mcur) * HMBUF) * 2u,
                       Mg, tid, q0, k0 + 64);
            CP_COMMIT();
        }
        if (it + 2 < 32) {
            const int nb = (it + 2) % 3;
            flash_cp_kv(sbase + (HK_OFF + nb*HKBUF)*2u,
                        sbase + (HV_OFF + nb*HVBUF)*2u, Kg, Vg, tid, k0 + 128);
            CP_COMMIT();
        }

        const unsigned sK = sbase + (unsigned)(HK_OFF + cur * HKBUF) * 2u;
        const unsigned sV = sbase + (unsigned)(HV_OFF + cur * HVBUF) * 2u;
        const unsigned sM = sbase + (unsigned)(HM_OFF + mcur * HMBUF) * 2u;

        // ---- S~ = Qs * K^T ----
        float s[2][8][4] = {};
        #pragma unroll
        for (int ks = 0; ks < 4; ks++) {
            const unsigned kboff = (unsigned)(ks * 16) * 2u;
            unsigned aq[2][4];
            #pragma unroll
            for (int mt = 0; mt < 2; mt++)
                ldm4(aq[mt][0], aq[mt][1], aq[mt][2], aq[mt][3],
                     sbase + (unsigned)((HQ_OFF + (w*32 + mt*16) * GSTRH)) * 2u
                           + kboff + aoff);
            #pragma unroll
            for (int p = 0; p < 4; p++) {
                unsigned b0, b1, b2, b3;
                ldm4(b0, b1, b2, b3,
                     sK + (unsigned)(p * 16 * GSTRH) * 2u + kboff + boff);
                mma16h(s[0][2*p],   aq[0][0], aq[0][1], aq[0][2], aq[0][3], b0, b1);
                mma16h(s[0][2*p+1], aq[0][0], aq[0][1], aq[0][2], aq[0][3], b2, b3);
                mma16h(s[1][2*p],   aq[1][0], aq[1][1], aq[1][2], aq[1][3], b0, b1);
                mma16h(s[1][2*p+1], aq[1][0], aq[1][1], aq[1][2], aq[1][3], b2, b3);
            }
        }

        // ---- P = exp2(s~ * mask)  (packed fp16: pack -> hmul2 -> h2exp2) ----
        // Fragment words pf[mt][kk][0..3] ARE the PV A-fragments.
        unsigned pf[2][4][4];
        #pragma unroll
        for (int mt = 0; mt < 2; mt++) {
            const unsigned sMr = sM + (unsigned)((w*32 + mt*16) * GSTRH) * 2u;
            #pragma unroll
            for (int p = 0; p < 4; p++) {
                unsigned m0, m1, m2, m3;
                ldm4(m0, m1, m2, m3, sMr + (unsigned)(p * 16) * 2u + aoff);
                pf[mt][p][0] = h2exp2u(hmul2u(pack_f16(s[mt][2*p][0],   s[mt][2*p][1]),   m0));
                pf[mt][p][1] = h2exp2u(hmul2u(pack_f16(s[mt][2*p][2],   s[mt][2*p][3]),   m1));
                pf[mt][p][2] = h2exp2u(hmul2u(pack_f16(s[mt][2*p+1][0], s[mt][2*p+1][1]), m2));
                pf[mt][p][3] = h2exp2u(hmul2u(pack_f16(s[mt][2*p+1][2], s[mt][2*p+1][3]), m3));
            }
        }

        // ---- O += P * V  (trans-ldmatrix B from natural-layout V) ----
        #pragma unroll
        for (int kk = 0; kk < 4; kk++) {
            const unsigned krow = (unsigned)(kk * 16 * GSTRH) * 2u;
            #pragma unroll
            for (int p = 0; p < 4; p++) {
                unsigned b0, b1, b2, b3;
                ldm4t(b0, b1, b2, b3,
                      sV + krow + (unsigned)(p * 16) * 2u + aoff);
                mma16h(o[0][2*p],   pf[0][kk][0], pf[0][kk][1], pf[0][kk][2], pf[0][kk][3], b0, b1);
                mma16h(o[0][2*p+1], pf[0][kk][0], pf[0][kk][1], pf[0][kk][2], pf[0][kk][3], b2, b3);
                mma16h(o[1][2*p],   pf[1][kk][0], pf[1][kk][1], pf[1][kk][2], pf[1][kk][3], b0, b1);
                mma16h(o[1][2*p+1], pf[1][kk][0], pf[1][kk][1], pf[1][kk][2], pf[1][kk][3], b2, b3);
            }
            {
                unsigned b0, b1;
                ldm2t(b0, b1, sV + krow + ooff);
                mma16h(ol[0], pf[0][kk][0], pf[0][kk][1], pf[0][kk][2], pf[0][kk][3], b0, b1);
                mma16h(ol[1], pf[1][kk][0], pf[1][kk][1], pf[1][kk][2], pf[1][kk][3], b0, b1);
            }
        }
    }

    // ---- l broadcast + normalize + write concat [B,N,M] fp16 ----
    #pragma unroll
    for (int mt = 0; mt < 2; mt++) {
        const float l0 = __shfl_sync(0xffffffffu, ol[mt][0], lane & 28);
        const float l1 = __shfl_sync(0xffffffffu, ol[mt][2], lane & 28);
        const float il0 = 1.0f / l0;
        const float il1 = 1.0f / l1;
        __half* Or0 = out + ((size_t)b * NN + qw + mt*16 + g) * MM + h * DKK;
        __half* Or1 = Or0 + 8 * MM;
        #pragma unroll
        for (int nt = 0; nt < 8; nt++) {
            const unsigned p0 = pack_f16(o[mt][nt][0] * il0, o[mt][nt][1] * il0);
            const unsigned p1 = pack_f16(o[mt][nt][2] * il1, o[mt][nt][3] * il1);
            *(unsigned*)(Or0 + nt * 8 + 2 * t) = p0;
            *(unsigned*)(Or1 + nt * 8 + 2 * t) = p1;
        }
    }
}

// ===========================================================================
extern "C" void kernel_launch(void* const* d_in, const int* in_sizes, int n_in,
                              void* d_out, int out_size)
{
    const float* x    = (const float*)d_in[0];
    const float* mask = (const float*)d_in[1];
    const float* Wq   = (const float*)d_in[2];
    const float* bq   = (const float*)d_in[3];
    const float* Wk   = (const float*)d_in[4];
    const float* bk   = (const float*)d_in[5];
    const float* Wv   = (const float*)d_in[6];
    const float* bv   = (const float*)d_in[7];
    const float* Wo   = (const float*)d_in[8];
    const float* bo   = (const float*)d_in[9];
    float* out = (float*)d_out;

    void *pxh, *pwh, *path, *pmh;
    cudaGetSymbolAddress(&pxh,  g_xh);
    cudaGetSymbolAddress(&pwh,  g_wh);
    cudaGetSymbolAddress(&path, g_ath);
    cudaGetSymbolAddress(&pmh,  g_mh);
    __half* xh  = (__half*)pxh;
    __half* wh  = (__half*)pwh;
    __half* ath = (__half*)path;
    __half* mh  = (__half*)pmh;

    cudaFuncSetAttribute(qkv_mma_kernel,
                         cudaFuncAttributeMaxDynamicSharedMemorySize, GEMM_SMEM);
    cudaFuncSetAttribute(out_mma_kernel,
                         cudaFuncAttributeMaxDynamicSharedMemorySize, GEMM_SMEM);
    cudaFuncSetAttribute(flash_mma_kernel,
                         cudaFuncAttributeMaxDynamicSharedMemorySize, FLASH_SMEM);

    // Convert inputs to fp16 once.
    cvt_f16_kernel<<<(ROWS*MM/4 + 255)/256, 256>>>(x, xh, ROWS*MM/4);
    cvt_f16_kernel<<<(BB*NN*NN/4 + 255)/256, 256>>>(mask, mh, BB*NN*NN/4);
    dim3 w_grid((MM*MM/4 + 255)/256, 4);
    cvt_w_kernel<<<w_grid, 256>>>(Wq, Wk, Wv, Wo, wh);

    // Fused Q/K/V projections (Q pre-scaled by 0.125*log2(e))
    const float qscale = 0.125f * 1.4426950408889634f;
    dim3 qkv_grid(MM/128, ROWS/128, 3);   // (8, 32, 3)
    qkv_mma_kernel<<<qkv_grid, 128, GEMM_SMEM>>>(xh, wh, bq, bk, bv, qscale);

    // Fused attention
    dim3 attn_grid(NN/128, HH, BB);       // (16, 16, 2)
    flash_mma_kernel<<<attn_grid, 128, FLASH_SMEM>>>(mh, ath);

    // Output projection (fp32 out)
    dim3 out_grid(MM/128, ROWS/128);      // (8, 32)
    out_mma_kernel<<<out_grid, 128, GEMM_SMEM>>>(ath, wh + 3*(size_t)MM*MM, bo, out);
}